// round 3
// baseline (speedup 1.0000x reference)
#include <cuda_runtime.h>
#include <math.h>

#define NMAX 200000
#define DFEAT 256
#define MNB   64
#define KSEL  3
#define NODES_PER_WARP 8

// Scratch (allocation-free): per-node projections.
__device__ float g_s_self[NMAX];
__device__ float g_s_all[NMAX];

// ---------------------------------------------------------------------------
// Kernel 1: one warp handles NODES_PER_WARP consecutive nodes. W hoisted into
// registers; x-row loads double-buffered so next node's LDG.128s are in flight
// during the current node's shfl-reduction chain.
// ---------------------------------------------------------------------------
__global__ void __launch_bounds__(256) score_kernel(const float* __restrict__ x,
                                                    const float* __restrict__ W,
                                                    const float* __restrict__ bias,
                                                    int N) {
    int warp = (blockIdx.x * 256 + threadIdx.x) >> 5;
    int lane = threadIdx.x & 31;
    int node0 = warp * NODES_PER_WARP;
    if (node0 >= N) return;

    const float4* wa4 = (const float4*)(W);          // W[0:256]
    const float4* wb4 = (const float4*)(W + DFEAT);  // W[256:512]
    float4 a0 = __ldg(wa4 + lane), a1 = __ldg(wa4 + lane + 32);
    float4 b0 = __ldg(wb4 + lane), b1 = __ldg(wb4 + lane + 32);
    float bb = bias[0];

    int nEnd = node0 + NODES_PER_WARP;
    if (nEnd > N) nEnd = N;

    const float4* xr = (const float4*)(x + (size_t)node0 * DFEAT);
    float4 x0 = __ldg(xr + lane);
    float4 x1 = __ldg(xr + lane + 32);

    for (int node = node0; node < nEnd; node++) {
        float4 c0 = x0, c1 = x1;
        if (node + 1 < nEnd) {                       // prefetch next row
            const float4* xn = (const float4*)(x + (size_t)(node + 1) * DFEAT);
            x0 = __ldg(xn + lane);
            x1 = __ldg(xn + lane + 32);
        }

        float sa, sb;
        sa  = c0.x * a0.x;          sa = fmaf(c0.y, a0.y, sa);
        sa  = fmaf(c0.z, a0.z, sa); sa = fmaf(c0.w, a0.w, sa);
        sa  = fmaf(c1.x, a1.x, sa); sa = fmaf(c1.y, a1.y, sa);
        sa  = fmaf(c1.z, a1.z, sa); sa = fmaf(c1.w, a1.w, sa);
        sb  = c0.x * b0.x;          sb = fmaf(c0.y, b0.y, sb);
        sb  = fmaf(c0.z, b0.z, sb); sb = fmaf(c0.w, b0.w, sb);
        sb  = fmaf(c1.x, b1.x, sb); sb = fmaf(c1.y, b1.y, sb);
        sb  = fmaf(c1.z, b1.z, sb); sb = fmaf(c1.w, b1.w, sb);
#pragma unroll
        for (int off = 16; off; off >>= 1) {
            sa += __shfl_xor_sync(0xffffffffu, sa, off);
            sb += __shfl_xor_sync(0xffffffffu, sb, off);
        }
        if (lane == 0) {
            g_s_self[node] = sa + bb;
            g_s_all[node]  = sb;
        }
    }
}

// Order-preserving float<->uint mapping (total order on floats).
__device__ __forceinline__ unsigned fkey(float f) {
    unsigned u = __float_as_uint(f);
    return (u & 0x80000000u) ? ~u : (u | 0x80000000u);
}
__device__ __forceinline__ float funkey(unsigned u) {
    unsigned b = (u & 0x80000000u) ? (u & 0x7fffffffu) : ~u;
    return __uint_as_float(b);
}

// ---------------------------------------------------------------------------
// Kernel 2: TWO nodes per warp, one per 16-lane segment. Each lane owns 4
// candidates (int4 neighbor load, 4 L2-resident gathers). Ranking on 32-bit
// keys of s_all (monotonic scoring => same order/ties as full score).
// Per selection round: 1 segmented REDUX.max + 1 ballot (+ffs) for the lowest
// position + 2 width-16 shfls. Ties break toward lowest column (jax top_k).
// exp/leaky computed only for the 3 winners.
// ---------------------------------------------------------------------------
__global__ void __launch_bounds__(256) topk_kernel(const int* __restrict__ neighbors,
                                                   const int* __restrict__ counts,
                                                   float* __restrict__ out,
                                                   int N) {
    int warp = (blockIdx.x * 256 + threadIdx.x) >> 5;
    int lane = threadIdx.x & 31;
    int half = lane >> 4;                 // segment id within warp
    int sub  = lane & 15;                 // lane within segment
    int node = warp * 2 + half;
    if (node >= N) return;

    unsigned mask = half ? 0xFFFF0000u : 0x0000FFFFu;

    const int4* nb = (const int4*)(neighbors + (size_t)node * MNB);
    int4 nbr = __ldg(nb + sub);           // positions 4*sub .. 4*sub+3
    int  cnt = __ldg(counts + node);
    int  base = sub * 4;

    // key 0 marks invalid/knocked-out; fkey(any float) > 0. cnt >= K, so the
    // top-3 are always real entries.
    unsigned k0 = (base + 0 < cnt) ? fkey(__ldg(g_s_all + nbr.x)) : 0u;
    unsigned k1 = (base + 1 < cnt) ? fkey(__ldg(g_s_all + nbr.y)) : 0u;
    unsigned k2 = (base + 2 < cnt) ? fkey(__ldg(g_s_all + nbr.z)) : 0u;
    unsigned k3 = (base + 3 < cnt) ? fkey(__ldg(g_s_all + nbr.w)) : 0u;

    unsigned winkey[KSEL];
    int      sel[KSEL];
#pragma unroll
    for (int t = 0; t < KSEL; t++) {
        unsigned lmax = k0 > k1 ? k0 : k1;
        unsigned lm2  = k2 > k3 ? k2 : k3;
        if (lm2 > lmax) lmax = lm2;

        unsigned m = __reduce_max_sync(mask, lmax);

        // Lowest segment-lane holding the max.
        unsigned bal = __ballot_sync(mask, lmax == m);
        unsigned balseg = half ? (bal >> 16) : (bal & 0xFFFFu);
        int wsub = __ffs((int)balseg) - 1;

        // Lowest slot within that lane holding the max.
        int li = 3;
        if (k2 == m) li = 2;
        if (k1 == m) li = 1;
        if (k0 == m) li = 0;
        int wli = __shfl_sync(mask, li, wsub, 16);   // uniform in segment

        int cand = (wli == 0) ? nbr.x : (wli == 1) ? nbr.y
                 : (wli == 2) ? nbr.z : nbr.w;       // wli uniform
        sel[t]    = __shfl_sync(mask, cand, wsub, 16);
        winkey[t] = m;

        if (sub == wsub) {                            // knock out winner
            if      (wli == 0) k0 = 0u;
            else if (wli == 1) k1 = 0u;
            else if (wli == 2) k2 = 0u;
            else               k3 = 0u;
        }
    }

    if (sub == 0) {
        float ss = g_s_self[node];
        size_t vb = (size_t)node * KSEL;
        float* osel = out + (size_t)N * KSEL;
#pragma unroll
        for (int t = 0; t < KSEL; t++) {
            float v = ss + funkey(winkey[t]);
            v = (v >= 0.f) ? v : 0.01f * v;          // leaky_relu (jax default)
            out[vb + t]  = expf(v);
            osel[vb + t] = (float)sel[t];            // exact: ids < 2^24
        }
    }
}

extern "C" void kernel_launch(void* const* d_in, const int* in_sizes, int n_in,
                              void* d_out, int out_size) {
    // metadata order: node_features, neighbors, neighbor_counts, W, b
    const float* x         = (const float*)d_in[0];
    const int*   neighbors = (const int*)d_in[1];
    const int*   counts    = (const int*)d_in[2];
    const float* W         = (const float*)d_in[3];
    const float* bias      = (const float*)d_in[4];

    int N = in_sizes[0] / DFEAT;
    if (N > NMAX) N = NMAX;

    int warps1  = (N + NODES_PER_WARP - 1) / NODES_PER_WARP;
    int blocks1 = (warps1 + 7) / 8;
    score_kernel<<<blocks1, 256>>>(x, W, bias, N);

    int warps2  = (N + 1) / 2;               // 2 nodes per warp
    int blocks2 = (warps2 + 7) / 8;
    topk_kernel<<<blocks2, 256>>>(neighbors, counts, (float*)d_out, N);
}

// round 4
// speedup vs baseline: 1.0487x; 1.0487x over previous
#include <cuda_runtime.h>
#include <math.h>

#define NMAX 200000
#define DFEAT 256
#define MNB   64
#define KSEL  3
#define NODES_PER_WARP 8

// Scratch (allocation-free): per-node projections.
__device__ float g_s_self[NMAX];
__device__ float g_s_all[NMAX];

// ---------------------------------------------------------------------------
// Kernel 1: one warp handles NODES_PER_WARP consecutive nodes. W hoisted into
// registers; x-row loads double-buffered across the node loop.
// ---------------------------------------------------------------------------
__global__ void __launch_bounds__(256) score_kernel(const float* __restrict__ x,
                                                    const float* __restrict__ W,
                                                    const float* __restrict__ bias,
                                                    int N) {
    int warp = (blockIdx.x * 256 + threadIdx.x) >> 5;
    int lane = threadIdx.x & 31;
    int node0 = warp * NODES_PER_WARP;
    if (node0 >= N) return;

    const float4* wa4 = (const float4*)(W);          // W[0:256]
    const float4* wb4 = (const float4*)(W + DFEAT);  // W[256:512]
    float4 a0 = __ldg(wa4 + lane), a1 = __ldg(wa4 + lane + 32);
    float4 b0 = __ldg(wb4 + lane), b1 = __ldg(wb4 + lane + 32);
    float bb = bias[0];

    int nEnd = node0 + NODES_PER_WARP;
    if (nEnd > N) nEnd = N;

    const float4* xr = (const float4*)(x + (size_t)node0 * DFEAT);
    float4 x0 = __ldg(xr + lane);
    float4 x1 = __ldg(xr + lane + 32);

    for (int node = node0; node < nEnd; node++) {
        float4 c0 = x0, c1 = x1;
        if (node + 1 < nEnd) {                       // prefetch next row
            const float4* xn = (const float4*)(x + (size_t)(node + 1) * DFEAT);
            x0 = __ldg(xn + lane);
            x1 = __ldg(xn + lane + 32);
        }

        float sa, sb;
        sa  = c0.x * a0.x;          sa = fmaf(c0.y, a0.y, sa);
        sa  = fmaf(c0.z, a0.z, sa); sa = fmaf(c0.w, a0.w, sa);
        sa  = fmaf(c1.x, a1.x, sa); sa = fmaf(c1.y, a1.y, sa);
        sa  = fmaf(c1.z, a1.z, sa); sa = fmaf(c1.w, a1.w, sa);
        sb  = c0.x * b0.x;          sb = fmaf(c0.y, b0.y, sb);
        sb  = fmaf(c0.z, b0.z, sb); sb = fmaf(c0.w, b0.w, sb);
        sb  = fmaf(c1.x, b1.x, sb); sb = fmaf(c1.y, b1.y, sb);
        sb  = fmaf(c1.w, b1.w, sb); sb = fmaf(c1.z, b1.z, sb);
#pragma unroll
        for (int off = 16; off; off >>= 1) {
            sa += __shfl_xor_sync(0xffffffffu, sa, off);
            sb += __shfl_xor_sync(0xffffffffu, sb, off);
        }
        if (lane == 0) {
            g_s_self[node] = sa + bb;
            g_s_all[node]  = sb;
        }
    }
}

// Order-preserving float<->uint mapping (total order on floats).
__device__ __forceinline__ unsigned fkey(float f) {
    unsigned u = __float_as_uint(f);
    return (u & 0x80000000u) ? ~u : (u | 0x80000000u);
}
__device__ __forceinline__ float funkey(unsigned u) {
    unsigned b = (u & 0x80000000u) ? (u & 0x7fffffffu) : ~u;
    return __uint_as_float(b);
}

// ---------------------------------------------------------------------------
// Kernel 2: TWO nodes per warp (16-lane segments), 4 candidate slots/lane.
// Ranking on 32-bit keys of s_all (monotone scoring => identical order).
// Tie-breaking by position is dropped: key ties only arise from duplicate
// neighbor indices, which carry identical (value, index) outputs either way.
// Per round: local max (3 IMNMX) + REDUX.max + ballot/ffs + 1 shfl +
// predicated knockout. Epilogue parallel over lanes 0..2 with __expf.
// ---------------------------------------------------------------------------
__global__ void __launch_bounds__(256) topk_kernel(const int* __restrict__ neighbors,
                                                   const int* __restrict__ counts,
                                                   float* __restrict__ out,
                                                   int N) {
    int warp = (blockIdx.x * 256 + threadIdx.x) >> 5;
    int lane = threadIdx.x & 31;
    int half = lane >> 4;                 // segment id within warp
    int sub  = lane & 15;                 // lane within segment
    int node = warp * 2 + half;
    if (node >= N) return;

    unsigned mask = half ? 0xFFFF0000u : 0x0000FFFFu;

    int  cnt  = __ldg(counts + node);
    int  base = sub * 4;

    int4 nbr = make_int4(0, 0, 0, 0);
    if (base < cnt) {                      // skip wholly-invalid int4 loads
        const int4* nb = (const int4*)(neighbors + (size_t)node * MNB);
        nbr = __ldg(nb + sub);             // positions 4*sub .. 4*sub+3
    }

    // key 0 marks invalid/knocked-out; fkey(any float) > 0. cnt >= K, so the
    // top-3 are always real entries.
    unsigned k0 = (base + 0 < cnt) ? fkey(__ldg(g_s_all + nbr.x)) : 0u;
    unsigned k1 = (base + 1 < cnt) ? fkey(__ldg(g_s_all + nbr.y)) : 0u;
    unsigned k2 = (base + 2 < cnt) ? fkey(__ldg(g_s_all + nbr.z)) : 0u;
    unsigned k3 = (base + 3 < cnt) ? fkey(__ldg(g_s_all + nbr.w)) : 0u;

    unsigned winkey[KSEL];
    int      sel[KSEL];
#pragma unroll
    for (int t = 0; t < KSEL; t++) {
        unsigned a = k0 > k1 ? k0 : k1;
        unsigned c = k2 > k3 ? k2 : k3;
        unsigned lmax = a > c ? a : c;

        unsigned m = __reduce_max_sync(mask, lmax);
        winkey[t] = m;

        unsigned bal = __ballot_sync(mask, lmax == m);
        unsigned balseg = half ? (bal >> 16) : (bal & 0xFFFFu);
        int wsub = __ffs((int)balseg) - 1;            // winning segment-lane

        // Each lane's own best slot + candidate (only winner lane's is used).
        int li = 3;
        if (k2 == m) li = 2;
        if (k1 == m) li = 1;
        if (k0 == m) li = 0;
        int candl = (li == 0) ? nbr.x : (li == 1) ? nbr.y
                  : (li == 2) ? nbr.z : nbr.w;
        sel[t] = __shfl_sync(mask, candl, wsub, 16);

        if (sub == wsub) {                            // knock out winner slot
            if      (li == 0) k0 = 0u;
            else if (li == 1) k1 = 0u;
            else if (li == 2) k2 = 0u;
            else              k3 = 0u;
        }
    }

    if (sub < KSEL) {                                 // parallel epilogue
        unsigned wk = (sub == 0) ? winkey[0] : (sub == 1) ? winkey[1] : winkey[2];
        int      sl = (sub == 0) ? sel[0]    : (sub == 1) ? sel[1]    : sel[2];
        float v = g_s_self[node] + funkey(wk);
        v = fmaxf(v, 0.01f * v);                      // leaky_relu (jax default)
        size_t vb = (size_t)node * KSEL + sub;
        out[vb] = __expf(v);
        out[(size_t)N * KSEL + vb] = (float)sl;       // exact: ids < 2^24
    }
}

extern "C" void kernel_launch(void* const* d_in, const int* in_sizes, int n_in,
                              void* d_out, int out_size) {
    // metadata order: node_features, neighbors, neighbor_counts, W, b
    const float* x         = (const float*)d_in[0];
    const int*   neighbors = (const int*)d_in[1];
    const int*   counts    = (const int*)d_in[2];
    const float* W         = (const float*)d_in[3];
    const float* bias      = (const float*)d_in[4];

    int N = in_sizes[0] / DFEAT;
    if (N > NMAX) N = NMAX;

    int warps1  = (N + NODES_PER_WARP - 1) / NODES_PER_WARP;
    int blocks1 = (warps1 + 7) / 8;
    score_kernel<<<blocks1, 256>>>(x, W, bias, N);

    int warps2  = (N + 1) / 2;               // 2 nodes per warp
    int blocks2 = (warps2 + 7) / 8;
    topk_kernel<<<blocks2, 256>>>(neighbors, counts, (float*)d_out, N);
}

// round 5
// speedup vs baseline: 1.1136x; 1.0619x over previous
#include <cuda_runtime.h>
#include <math.h>

#define NMAX 200000
#define DFEAT 256
#define MNB   64
#define KSEL  3
#define NODES_PER_WARP 8

// Scratch (allocation-free): per-node projections.
__device__ float g_s_self[NMAX];
__device__ float g_s_all[NMAX];

// ---------------------------------------------------------------------------
// Kernel 1: one warp handles 8 nodes in 2 batches of 4. All 4 rows of a batch
// are loaded up-front (8 LDG.128 per lane in flight, MLP 8), then the 4
// reduction chains run interleaved for shfl ILP.
// ---------------------------------------------------------------------------
__global__ void __launch_bounds__(256) score_kernel(const float* __restrict__ x,
                                                    const float* __restrict__ W,
                                                    const float* __restrict__ bias,
                                                    int N) {
    int warp = (blockIdx.x * 256 + threadIdx.x) >> 5;
    int lane = threadIdx.x & 31;
    int node0 = warp * NODES_PER_WARP;
    if (node0 >= N) return;

    const float4* wa4 = (const float4*)(W);          // W[0:256]
    const float4* wb4 = (const float4*)(W + DFEAT);  // W[256:512]
    float4 a0 = __ldg(wa4 + lane), a1 = __ldg(wa4 + lane + 32);
    float4 b0 = __ldg(wb4 + lane), b1 = __ldg(wb4 + lane + 32);
    float bb = bias[0];

#pragma unroll
    for (int batch = 0; batch < NODES_PER_WARP; batch += 4) {
        int nb0 = node0 + batch;

        float4 v0[4], v1[4];
#pragma unroll
        for (int i = 0; i < 4; i++) {
            int n = nb0 + i;
            if (n < N) {
                const float4* xr = (const float4*)(x + (size_t)n * DFEAT);
                v0[i] = __ldg(xr + lane);
                v1[i] = __ldg(xr + lane + 32);
            }
        }

        float sa[4], sb[4];
#pragma unroll
        for (int i = 0; i < 4; i++) {
            float4 c0 = v0[i], c1 = v1[i];
            float ta, tb;
            ta  = c0.x * a0.x;          ta = fmaf(c0.y, a0.y, ta);
            ta  = fmaf(c0.z, a0.z, ta); ta = fmaf(c0.w, a0.w, ta);
            ta  = fmaf(c1.x, a1.x, ta); ta = fmaf(c1.y, a1.y, ta);
            ta  = fmaf(c1.z, a1.z, ta); ta = fmaf(c1.w, a1.w, ta);
            tb  = c0.x * b0.x;          tb = fmaf(c0.y, b0.y, tb);
            tb  = fmaf(c0.z, b0.z, tb); tb = fmaf(c0.w, b0.w, tb);
            tb  = fmaf(c1.x, b1.x, tb); tb = fmaf(c1.y, b1.y, tb);
            tb  = fmaf(c1.z, b1.z, tb); tb = fmaf(c1.w, b1.w, tb);
            sa[i] = ta; sb[i] = tb;
        }

        // Interleaved butterfly reductions: 8 independent shfls per level.
#pragma unroll
        for (int off = 16; off; off >>= 1) {
#pragma unroll
            for (int i = 0; i < 4; i++) {
                sa[i] += __shfl_xor_sync(0xffffffffu, sa[i], off);
                sb[i] += __shfl_xor_sync(0xffffffffu, sb[i], off);
            }
        }
        if (lane == 0) {
#pragma unroll
            for (int i = 0; i < 4; i++) {
                int n = nb0 + i;
                if (n < N) {
                    g_s_self[n] = sa[i] + bb;
                    g_s_all[n]  = sb[i];
                }
            }
        }
    }
}

// Order-preserving float<->uint mapping (total order on floats).
__device__ __forceinline__ unsigned fkey(float f) {
    unsigned u = __float_as_uint(f);
    return (u & 0x80000000u) ? ~u : (u | 0x80000000u);
}
__device__ __forceinline__ float funkey(unsigned u) {
    unsigned b = (u & 0x80000000u) ? (u & 0x7fffffffu) : ~u;
    return __uint_as_float(b);
}

// ---------------------------------------------------------------------------
// Kernel 2: TWO nodes per warp (16-lane segments), 4 candidate slots/lane.
// Each lane presorts its 4 (key,cand) pairs descending (5 compare-swaps);
// selection rounds then only touch the per-lane HEAD: REDUX.max + ballot/ffs
// + one shfl of winner's head cand + predicated shift-pop. Invalid slots are
// key=0 and sort to the bottom; a lane pops at most 3 times so no re-zeroing.
// exp/leaky computed only for the 3 winners, on lanes 0..2 in parallel.
// ---------------------------------------------------------------------------
__global__ void __launch_bounds__(256) topk_kernel(const int* __restrict__ neighbors,
                                                   const int* __restrict__ counts,
                                                   float* __restrict__ out,
                                                   int N) {
    int warp = (blockIdx.x * 256 + threadIdx.x) >> 5;
    int lane = threadIdx.x & 31;
    int half = lane >> 4;                 // segment id within warp
    int sub  = lane & 15;                 // lane within segment
    int node = warp * 2 + half;
    if (node >= N) return;

    unsigned mask = half ? 0xFFFF0000u : 0x0000FFFFu;

    int  cnt  = __ldg(counts + node);
    int  base = sub * 4;

    int4 nbr = make_int4(0, 0, 0, 0);
    if (base < cnt) {                      // skip wholly-invalid int4 loads
        const int4* nb = (const int4*)(neighbors + (size_t)node * MNB);
        nbr = __ldg(nb + sub);             // positions 4*sub .. 4*sub+3
    }

    // key 0 marks invalid; fkey(any float) > 0. Predicated-off gathers emit
    // no L1 wavefront (load-bearing for the memory floor).
    unsigned k0 = (base + 0 < cnt) ? fkey(__ldg(g_s_all + nbr.x)) : 0u;
    unsigned k1 = (base + 1 < cnt) ? fkey(__ldg(g_s_all + nbr.y)) : 0u;
    unsigned k2 = (base + 2 < cnt) ? fkey(__ldg(g_s_all + nbr.z)) : 0u;
    unsigned k3 = (base + 3 < cnt) ? fkey(__ldg(g_s_all + nbr.w)) : 0u;
    int c0 = nbr.x, c1 = nbr.y, c2 = nbr.z, c3 = nbr.w;

    // Presort the 4 (key,cand) pairs descending by key (stable on ties).
#define CSWAP(ka, ca, kb, cb)                                        \
    { bool sw = (kb) > (ka);                                         \
      unsigned tk = sw ? (kb) : (ka); (kb) = sw ? (ka) : (kb); (ka) = tk; \
      int tc = sw ? (cb) : (ca); (cb) = sw ? (ca) : (cb); (ca) = tc; }
    CSWAP(k0, c0, k1, c1)
    CSWAP(k2, c2, k3, c3)
    CSWAP(k0, c0, k2, c2)
    CSWAP(k1, c1, k3, c3)
    CSWAP(k1, c1, k2, c2)
#undef CSWAP

    unsigned wk0, wk1, wk2;
    int      sl0, sl1, sl2;
#pragma unroll
    for (int t = 0; t < KSEL; t++) {
        unsigned m = __reduce_max_sync(mask, k0);
        unsigned bal = __ballot_sync(mask, k0 == m);
        unsigned balseg = half ? (bal >> 16) : (bal & 0xFFFFu);
        int wsub = __ffs((int)balseg) - 1;           // winning segment-lane
        int s = __shfl_sync(mask, c0, wsub, 16);

        if (t == 0) { wk0 = m; sl0 = s; }
        else if (t == 1) { wk1 = m; sl1 = s; }
        else { wk2 = m; sl2 = s; }

        if (sub == wsub) {                            // pop winner's head
            k0 = k1; c0 = c1;
            k1 = k2; c1 = c2;
            k2 = k3; c2 = c3;
        }
    }

    if (sub < KSEL) {                                 // parallel epilogue
        unsigned wk = (sub == 0) ? wk0 : (sub == 1) ? wk1 : wk2;
        int      sl = (sub == 0) ? sl0 : (sub == 1) ? sl1 : sl2;
        float v = g_s_self[node] + funkey(wk);
        v = fmaxf(v, 0.01f * v);                      // leaky_relu (jax default)
        size_t vb = (size_t)node * KSEL + sub;
        out[vb] = __expf(v);
        out[(size_t)N * KSEL + vb] = (float)sl;       // exact: ids < 2^24
    }
}

extern "C" void kernel_launch(void* const* d_in, const int* in_sizes, int n_in,
                              void* d_out, int out_size) {
    // metadata order: node_features, neighbors, neighbor_counts, W, b
    const float* x         = (const float*)d_in[0];
    const int*   neighbors = (const int*)d_in[1];
    const int*   counts    = (const int*)d_in[2];
    const float* W         = (const float*)d_in[3];
    const float* bias      = (const float*)d_in[4];

    int N = in_sizes[0] / DFEAT;
    if (N > NMAX) N = NMAX;

    int warps1  = (N + NODES_PER_WARP - 1) / NODES_PER_WARP;
    int blocks1 = (warps1 + 7) / 8;
    score_kernel<<<blocks1, 256>>>(x, W, bias, N);

    int warps2  = (N + 1) / 2;               // 2 nodes per warp
    int blocks2 = (warps2 + 7) / 8;
    topk_kernel<<<blocks2, 256>>>(neighbors, counts, (float*)d_out, N);
}